// round 13
// baseline (speedup 1.0000x reference)
#include <cuda_runtime.h>
#include <math.h>

// Problem constants (fixed shapes from reference setup_inputs)
#define BB 32
#define SS 64
#define HH 256
#define CELLS_PER_BATCH (SS * SS)   // 4096
#define NBLOCKS (BB * 32)           // 1024: 32 blocks per batch
#define EPSF 1e-8f

// Per-block partial sums. Written unconditionally by every block each launch,
// so they never need zero-initialization (graph-replay safe).
__device__ float g_part_p[NBLOCKS];
__device__ float g_part_n[NBLOCKS];
// Completion counter for the last-block reduction. Starts at 0 (module load);
// the last block resets it to 0 after use, so every replay sees 0.
__device__ unsigned int g_done;

// ---------------------------------------------------------------------------
// Single fused kernel.
//   grid = 1024 blocks x 256 threads; block bi handles batch bi>>5,
//   warp w handles 16 consecutive cells.
//   - invq computed per-warp from the q registers it already loads (no init pass)
//   - mask-gated loads skip ~65% of tmap HBM traffic
//   - cells processed in pairs for 4 LDG.128 in flight
//   - per-block partials + last-block epilogue (no global atomics on sums)
// ---------------------------------------------------------------------------
__global__ void __launch_bounds__(256) cl_fused_kernel(
    const float* __restrict__ tmap,
    const float* __restrict__ pos_query,
    const int*   __restrict__ mpos,
    const int*   __restrict__ mneg,
    float*       __restrict__ out)
{
    const int b        = blockIdx.x >> 5;        // 32 blocks per batch
    const int blk_in_b = blockIdx.x & 31;
    const int wid      = threadIdx.x >> 5;
    const int lane     = threadIdx.x & 31;

    // This warp's 16 consecutive cells within batch b
    const int cell0 = b * CELLS_PER_BATCH + blk_in_b * 128 + wid * 16;

    // Query chunk for this lane (same for all 16 cells; stays in registers)
    const float4* qp = reinterpret_cast<const float4*>(pos_query + (size_t)b * HH);
    const float4 q0 = qp[lane];
    const float4 q1 = qp[lane + 32];

    // invq = 1/(||q||+eps), computed per-warp from registers (butterfly -> all lanes)
    float qq = q0.x * q0.x + q0.y * q0.y + q0.z * q0.z + q0.w * q0.w
             + q1.x * q1.x + q1.y * q1.y + q1.z * q1.z + q1.w * q1.w;
    #pragma unroll
    for (int o = 16; o > 0; o >>= 1)
        qq += __shfl_xor_sync(0xFFFFFFFFu, qq, o);
    const float invq = 1.0f / (sqrtf(qq) + EPSF);

    float psum = 0.0f, nsum = 0.0f;

    // Process cells in pairs: up to 4 independent LDG.128 in flight.
    #pragma unroll 2
    for (int k = 0; k < 16; k += 2) {
        const int c0 = cell0 + k;
        const int c1 = c0 + 1;
        const int pm0 = mpos[c0], nm0 = mneg[c0];
        const int pm1 = mpos[c1], nm1 = mneg[c1];
        const bool l0 = (pm0 | nm0) != 0;
        const bool l1 = (pm1 | nm1) != 0;
        if (!(l0 | l1)) continue;                // both dead: no tmap reads

        float dq0 = 0.0f, dt0 = 1.0f, dq1 = 0.0f, dt1 = 1.0f;
        if (l0) {
            const float4* tp = reinterpret_cast<const float4*>(tmap + (size_t)c0 * HH);
            const float4 t0 = tp[lane];
            const float4 t1 = tp[lane + 32];
            dq0 = t0.x * q0.x + t0.y * q0.y + t0.z * q0.z + t0.w * q0.w
                + t1.x * q1.x + t1.y * q1.y + t1.z * q1.z + t1.w * q1.w;
            dt0 = t0.x * t0.x + t0.y * t0.y + t0.z * t0.z + t0.w * t0.w
                + t1.x * t1.x + t1.y * t1.y + t1.z * t1.z + t1.w * t1.w;
        }
        if (l1) {
            const float4* tp = reinterpret_cast<const float4*>(tmap + (size_t)c1 * HH);
            const float4 t0 = tp[lane];
            const float4 t1 = tp[lane + 32];
            dq1 = t0.x * q0.x + t0.y * q0.y + t0.z * q0.z + t0.w * q0.w
                + t1.x * q1.x + t1.y * q1.y + t1.z * q1.z + t1.w * q1.w;
            dt1 = t0.x * t0.x + t0.y * t0.y + t0.z * t0.z + t0.w * t0.w
                + t1.x * t1.x + t1.y * t1.y + t1.z * t1.z + t1.w * t1.w;
        }

        if (l0 & l1) {
            #pragma unroll
            for (int o = 16; o > 0; o >>= 1) {
                dq0 += __shfl_xor_sync(0xFFFFFFFFu, dq0, o);
                dt0 += __shfl_xor_sync(0xFFFFFFFFu, dt0, o);
                dq1 += __shfl_xor_sync(0xFFFFFFFFu, dq1, o);
                dt1 += __shfl_xor_sync(0xFFFFFFFFu, dt1, o);
            }
        } else if (l0) {
            #pragma unroll
            for (int o = 16; o > 0; o >>= 1) {
                dq0 += __shfl_xor_sync(0xFFFFFFFFu, dq0, o);
                dt0 += __shfl_xor_sync(0xFFFFFFFFu, dt0, o);
            }
        } else {
            #pragma unroll
            for (int o = 16; o > 0; o >>= 1) {
                dq1 += __shfl_xor_sync(0xFFFFFFFFu, dq1, o);
                dt1 += __shfl_xor_sync(0xFFFFFFFFu, dt1, o);
            }
        }

        // s = dot(t,q)/||t||/(||q||+eps); the reference's inner renormalize
        // (||u||+eps, ||u||~=1) perturbs s by ~1e-7 << tolerance.
        if (l0) {
            const float e = expf(dq0 * rsqrtf(dt0) * invq);   // TAO = 1.0
            if (pm0) psum += e;
            if (nm0) nsum += e;
        }
        if (l1) {
            const float e = expf(dq1 * rsqrtf(dt1) * invq);
            if (pm1) psum += e;
            if (nm1) nsum += e;
        }
    }

    // Block reduction -> per-block partial (unconditional write: no init needed)
    __shared__ float s_p[8];
    __shared__ float s_n[8];
    if (lane == 0) { s_p[wid] = psum; s_n[wid] = nsum; }
    __syncthreads();

    __shared__ bool s_last;
    if (threadIdx.x == 0) {
        float ap = 0.0f, an = 0.0f;
        #pragma unroll
        for (int i = 0; i < 8; i++) { ap += s_p[i]; an += s_n[i]; }
        g_part_p[blockIdx.x] = ap;
        g_part_n[blockIdx.x] = an;
        __threadfence();                          // partials visible before count
        unsigned int prev = atomicAdd(&g_done, 1u);
        s_last = (prev == NBLOCKS - 1u);
    }
    __syncthreads();
    if (!s_last) return;

    // ---- Last block: per-batch loss + average ----
    __threadfence();                              // acquire all partials
    // Warp w handles batches w, w+8, w+16, w+24; lane reads one block partial.
    float li_acc = 0.0f;
    int   v_acc  = 0;
    #pragma unroll
    for (int r = 0; r < 4; r++) {
        const int bb = wid + r * 8;
        float p = g_part_p[bb * 32 + lane];
        float n = g_part_n[bb * 32 + lane];
        #pragma unroll
        for (int o = 16; o > 0; o >>= 1) {
            p += __shfl_xor_sync(0xFFFFFFFFu, p, o);
            n += __shfl_xor_sync(0xFFFFFFFFu, n, o);
        }
        // valid(b) = nonempty pos & neg sets <=> both sums > 0 (exp > 0)
        if (lane == 0 && p > 0.0f && n > 0.0f) {
            li_acc += -logf(p / (p + n + EPSF));
            v_acc  += 1;
        }
    }
    __shared__ float s_li[8];
    __shared__ int   s_v[8];
    if (lane == 0) { s_li[wid] = li_acc; s_v[wid] = v_acc; }
    __syncthreads();
    if (threadIdx.x == 0) {
        float li = 0.0f; int v = 0;
        #pragma unroll
        for (int i = 0; i < 8; i++) { li += s_li[i]; v += s_v[i]; }
        out[0] = li / (float)(v > 0 ? v : 1);
        g_done = 0u;                              // reset for next graph replay
    }
}

// ---------------------------------------------------------------------------
// Launch. Input order (metadata / setup_inputs dict order):
//   d_in[0] = pos_query  (B,H)     float32
//   d_in[1] = tmap       (B,S,S,H) float32
//   d_in[2] = mask2d_pos (B,S,S)   bool -> int32
//   d_in[3] = mask2d_neg (B,S,S)   bool -> int32
// Output: scalar float32.
// ---------------------------------------------------------------------------
extern "C" void kernel_launch(void* const* d_in, const int* in_sizes, int n_in,
                              void* d_out, int out_size) {
    (void)in_sizes; (void)n_in; (void)out_size;
    const float* pos_query = (const float*)d_in[0];
    const float* tmap      = (const float*)d_in[1];
    const int*   mpos      = (const int*)d_in[2];
    const int*   mneg      = (const int*)d_in[3];
    float*       out       = (float*)d_out;

    cl_fused_kernel<<<NBLOCKS, 256>>>(tmap, pos_query, mpos, mneg, out);
}

// round 14
// speedup vs baseline: 1.0135x; 1.0135x over previous
#include <cuda_runtime.h>
#include <math.h>

// Problem constants (fixed shapes from reference setup_inputs)
#define BB 32
#define SS 64
#define HH 256
#define CELLS_PER_BATCH (SS * SS)   // 4096
#define NBLOCKS (BB * 32)           // 1024: 32 blocks per batch
#define EPSF 1e-8f

// Per-block partial sums. Written unconditionally by every block each launch,
// so they never need zero-initialization (graph-replay safe).
__device__ float g_part_p[NBLOCKS];
__device__ float g_part_n[NBLOCKS];
// Completion counter for the last-block reduction. Starts at 0 (module load);
// the last block resets it to 0 after use, so every replay sees 0.
__device__ unsigned int g_done;

// ---------------------------------------------------------------------------
// Single fused kernel.
//   grid = 1024 blocks x 256 threads; block bi handles batch bi>>5,
//   warp w handles 16 consecutive cells.
//   - invq computed per-warp from the q registers it already loads (no init pass)
//   - mask-gated loads skip ~65% of tmap HBM traffic
//   - cells processed in pairs for 4 LDG.128 in flight
//   - per-block partials + last-block epilogue (no global atomics on sums)
// ---------------------------------------------------------------------------
__global__ void __launch_bounds__(256) cl_fused_kernel(
    const float* __restrict__ tmap,
    const float* __restrict__ pos_query,
    const int*   __restrict__ mpos,
    const int*   __restrict__ mneg,
    float*       __restrict__ out)
{
    const int b        = blockIdx.x >> 5;        // 32 blocks per batch
    const int blk_in_b = blockIdx.x & 31;
    const int wid      = threadIdx.x >> 5;
    const int lane     = threadIdx.x & 31;

    // This warp's 16 consecutive cells within batch b
    const int cell0 = b * CELLS_PER_BATCH + blk_in_b * 128 + wid * 16;

    // Query chunk for this lane (same for all 16 cells; stays in registers)
    const float4* qp = reinterpret_cast<const float4*>(pos_query + (size_t)b * HH);
    const float4 q0 = qp[lane];
    const float4 q1 = qp[lane + 32];

    // invq = 1/(||q||+eps), computed per-warp from registers (butterfly -> all lanes)
    float qq = q0.x * q0.x + q0.y * q0.y + q0.z * q0.z + q0.w * q0.w
             + q1.x * q1.x + q1.y * q1.y + q1.z * q1.z + q1.w * q1.w;
    #pragma unroll
    for (int o = 16; o > 0; o >>= 1)
        qq += __shfl_xor_sync(0xFFFFFFFFu, qq, o);
    const float invq = 1.0f / (sqrtf(qq) + EPSF);

    float psum = 0.0f, nsum = 0.0f;

    // Process cells in pairs: up to 4 independent LDG.128 in flight.
    #pragma unroll 2
    for (int k = 0; k < 16; k += 2) {
        const int c0 = cell0 + k;
        const int c1 = c0 + 1;
        const int pm0 = mpos[c0], nm0 = mneg[c0];
        const int pm1 = mpos[c1], nm1 = mneg[c1];
        const bool l0 = (pm0 | nm0) != 0;
        const bool l1 = (pm1 | nm1) != 0;
        if (!(l0 | l1)) continue;                // both dead: no tmap reads

        float dq0 = 0.0f, dt0 = 1.0f, dq1 = 0.0f, dt1 = 1.0f;
        if (l0) {
            const float4* tp = reinterpret_cast<const float4*>(tmap + (size_t)c0 * HH);
            const float4 t0 = tp[lane];
            const float4 t1 = tp[lane + 32];
            dq0 = t0.x * q0.x + t0.y * q0.y + t0.z * q0.z + t0.w * q0.w
                + t1.x * q1.x + t1.y * q1.y + t1.z * q1.z + t1.w * q1.w;
            dt0 = t0.x * t0.x + t0.y * t0.y + t0.z * t0.z + t0.w * t0.w
                + t1.x * t1.x + t1.y * t1.y + t1.z * t1.z + t1.w * t1.w;
        }
        if (l1) {
            const float4* tp = reinterpret_cast<const float4*>(tmap + (size_t)c1 * HH);
            const float4 t0 = tp[lane];
            const float4 t1 = tp[lane + 32];
            dq1 = t0.x * q0.x + t0.y * q0.y + t0.z * q0.z + t0.w * q0.w
                + t1.x * q1.x + t1.y * q1.y + t1.z * q1.z + t1.w * q1.w;
            dt1 = t0.x * t0.x + t0.y * t0.y + t0.z * t0.z + t0.w * t0.w
                + t1.x * t1.x + t1.y * t1.y + t1.z * t1.z + t1.w * t1.w;
        }

        if (l0 & l1) {
            #pragma unroll
            for (int o = 16; o > 0; o >>= 1) {
                dq0 += __shfl_xor_sync(0xFFFFFFFFu, dq0, o);
                dt0 += __shfl_xor_sync(0xFFFFFFFFu, dt0, o);
                dq1 += __shfl_xor_sync(0xFFFFFFFFu, dq1, o);
                dt1 += __shfl_xor_sync(0xFFFFFFFFu, dt1, o);
            }
        } else if (l0) {
            #pragma unroll
            for (int o = 16; o > 0; o >>= 1) {
                dq0 += __shfl_xor_sync(0xFFFFFFFFu, dq0, o);
                dt0 += __shfl_xor_sync(0xFFFFFFFFu, dt0, o);
            }
        } else {
            #pragma unroll
            for (int o = 16; o > 0; o >>= 1) {
                dq1 += __shfl_xor_sync(0xFFFFFFFFu, dq1, o);
                dt1 += __shfl_xor_sync(0xFFFFFFFFu, dt1, o);
            }
        }

        // s = dot(t,q)/||t||/(||q||+eps); the reference's inner renormalize
        // (||u||+eps, ||u||~=1) perturbs s by ~1e-7 << tolerance.
        if (l0) {
            const float e = expf(dq0 * rsqrtf(dt0) * invq);   // TAO = 1.0
            if (pm0) psum += e;
            if (nm0) nsum += e;
        }
        if (l1) {
            const float e = expf(dq1 * rsqrtf(dt1) * invq);
            if (pm1) psum += e;
            if (nm1) nsum += e;
        }
    }

    // Block reduction -> per-block partial (unconditional write: no init needed)
    __shared__ float s_p[8];
    __shared__ float s_n[8];
    if (lane == 0) { s_p[wid] = psum; s_n[wid] = nsum; }
    __syncthreads();

    __shared__ bool s_last;
    if (threadIdx.x == 0) {
        float ap = 0.0f, an = 0.0f;
        #pragma unroll
        for (int i = 0; i < 8; i++) { ap += s_p[i]; an += s_n[i]; }
        g_part_p[blockIdx.x] = ap;
        g_part_n[blockIdx.x] = an;
        __threadfence();                          // partials visible before count
        unsigned int prev = atomicAdd(&g_done, 1u);
        s_last = (prev == NBLOCKS - 1u);
    }
    __syncthreads();
    if (!s_last) return;

    // ---- Last block: per-batch loss + average ----
    __threadfence();                              // acquire all partials
    // Warp w handles batches w, w+8, w+16, w+24; lane reads one block partial.
    float li_acc = 0.0f;
    int   v_acc  = 0;
    #pragma unroll
    for (int r = 0; r < 4; r++) {
        const int bb = wid + r * 8;
        float p = g_part_p[bb * 32 + lane];
        float n = g_part_n[bb * 32 + lane];
        #pragma unroll
        for (int o = 16; o > 0; o >>= 1) {
            p += __shfl_xor_sync(0xFFFFFFFFu, p, o);
            n += __shfl_xor_sync(0xFFFFFFFFu, n, o);
        }
        // valid(b) = nonempty pos & neg sets <=> both sums > 0 (exp > 0)
        if (lane == 0 && p > 0.0f && n > 0.0f) {
            li_acc += -logf(p / (p + n + EPSF));
            v_acc  += 1;
        }
    }
    __shared__ float s_li[8];
    __shared__ int   s_v[8];
    if (lane == 0) { s_li[wid] = li_acc; s_v[wid] = v_acc; }
    __syncthreads();
    if (threadIdx.x == 0) {
        float li = 0.0f; int v = 0;
        #pragma unroll
        for (int i = 0; i < 8; i++) { li += s_li[i]; v += s_v[i]; }
        out[0] = li / (float)(v > 0 ? v : 1);
        g_done = 0u;                              // reset for next graph replay
    }
}

// ---------------------------------------------------------------------------
// Launch. Input order (metadata / setup_inputs dict order):
//   d_in[0] = pos_query  (B,H)     float32
//   d_in[1] = tmap       (B,S,S,H) float32
//   d_in[2] = mask2d_pos (B,S,S)   bool -> int32
//   d_in[3] = mask2d_neg (B,S,S)   bool -> int32
// Output: scalar float32.
// ---------------------------------------------------------------------------
extern "C" void kernel_launch(void* const* d_in, const int* in_sizes, int n_in,
                              void* d_out, int out_size) {
    (void)in_sizes; (void)n_in; (void)out_size;
    const float* pos_query = (const float*)d_in[0];
    const float* tmap      = (const float*)d_in[1];
    const int*   mpos      = (const int*)d_in[2];
    const int*   mneg      = (const int*)d_in[3];
    float*       out       = (float*)d_out;

    cl_fused_kernel<<<NBLOCKS, 256>>>(tmap, pos_query, mpos, mneg, out);
}